// round 13
// baseline (speedup 1.0000x reference)
#include <cuda_runtime.h>
#include <stdint.h>

// ---------------------------------------------------------------------------
// Persistent fp32 RNN, k-pair packed f32x2, WIDE thread tile (j8 x b4).
//
// out[t] = tanh(x[t] @ Wi^T + h @ Wh^T),  h = out[t]
//
// 8 batch-groups x 16 H-slice CTAs = 128 CTAs, 256 threads (8 warps),
// 255-reg budget. Lanes: jq=lane&3 (8 j's), bp=(lane>>2)&3 (4 b's),
// kh=lane>>4 (k-half; interleaved kp rows). 16 virtual k-chunks x 24 kp.
// Inner: 6 LDS.128 -> 32 fma2 per kp (0.67 FMA/B vs 0.5 before).
// Sync protocol identical to R6 (best known): threadfence + S2 + tid0
// release; per-warp producer spin (2 producers/warp, R8 geometry).
// ---------------------------------------------------------------------------

namespace {
constexpr int kT = 1024, kB = 128, kI = 256, kH = 512;
constexpr int NG = 8, BG = 16, NC = 16, JC = 32;
constexpr int NTHR = 256, NWARP = 8;
constexpr int KP_H = kH / 2;          // 256
constexpr int KP_X = kI / 2;          // 128
constexpr int KPT  = KP_H + KP_X;     // 384

constexpr int WS_STRIDE = 34;         // u64 per weight row
constexpr int HD_STRIDE = 18;         // u64 per Hd row (16 cols + pad)
constexpr int PS_STRIDE = 33;         // floats per Ps row (odd -> bank spread)
constexpr int PS_ROWS   = 32 * 8;     // 16 chunks x 16 batches? -> 256 rows
constexpr int PS_FLOATS = PS_ROWS * PS_STRIDE;      // 8448

constexpr int OFF_WS = 0;
constexpr int OFF_HD = KPT * WS_STRIDE;             // 13056 u64
constexpr int OFF_PS = OFF_HD + KPT * HD_STRIDE;    // 19968 u64
constexpr int OFF_AUX = OFF_PS + (PS_FLOATS + 1) / 2;
constexpr int SMEM_U64 = OFF_AUX + 1;
constexpr size_t SMEM_BYTES = size_t(SMEM_U64) * 8; // ~189 KB
}

__device__ unsigned g_rnn_flag[NG * NC];   // zero-init; monotonic forever

__device__ __forceinline__ void fma2(unsigned long long& acc,
                                     unsigned long long a,
                                     unsigned long long b) {
    asm("fma.rn.f32x2 %0, %1, %2, %0;" : "+l"(acc) : "l"(a), "l"(b));
}

// one kp row: 8 j (w0..w3, mi order {0,1,4,5,2,3,6,7}) x 4 b (h0,h1)
#define STEP32(wp, hp)                                                       \
    do {                                                                     \
        const ulonglong2 w0 = *reinterpret_cast<const ulonglong2*>(wp);      \
        const ulonglong2 w1 = *reinterpret_cast<const ulonglong2*>((wp)+2);  \
        const ulonglong2 w2 = *reinterpret_cast<const ulonglong2*>((wp)+16); \
        const ulonglong2 w3 = *reinterpret_cast<const ulonglong2*>((wp)+18); \
        const ulonglong2 h0 = *reinterpret_cast<const ulonglong2*>(hp);      \
        const ulonglong2 h1 = *reinterpret_cast<const ulonglong2*>((hp)+2);  \
        fma2(acc[0],  w0.x, h0.x); fma2(acc[1],  w0.x, h0.y);                \
        fma2(acc[2],  w0.x, h1.x); fma2(acc[3],  w0.x, h1.y);                \
        fma2(acc[4],  w0.y, h0.x); fma2(acc[5],  w0.y, h0.y);                \
        fma2(acc[6],  w0.y, h1.x); fma2(acc[7],  w0.y, h1.y);                \
        fma2(acc[8],  w1.x, h0.x); fma2(acc[9],  w1.x, h0.y);                \
        fma2(acc[10], w1.x, h1.x); fma2(acc[11], w1.x, h1.y);                \
        fma2(acc[12], w1.y, h0.x); fma2(acc[13], w1.y, h0.y);                \
        fma2(acc[14], w1.y, h1.x); fma2(acc[15], w1.y, h1.y);                \
        fma2(acc[16], w2.x, h0.x); fma2(acc[17], w2.x, h0.y);                \
        fma2(acc[18], w2.x, h1.x); fma2(acc[19], w2.x, h1.y);                \
        fma2(acc[20], w2.y, h0.x); fma2(acc[21], w2.y, h0.y);                \
        fma2(acc[22], w2.y, h1.x); fma2(acc[23], w2.y, h1.y);                \
        fma2(acc[24], w3.x, h0.x); fma2(acc[25], w3.x, h0.y);                \
        fma2(acc[26], w3.x, h1.x); fma2(acc[27], w3.x, h1.y);                \
        fma2(acc[28], w3.y, h0.x); fma2(acc[29], w3.y, h0.y);                \
        fma2(acc[30], w3.y, h1.x); fma2(acc[31], w3.y, h1.y);                \
    } while (0)

__global__ void __launch_bounds__(NTHR, 1)
rnn_wide_kernel(const float* __restrict__ x,
                const float* __restrict__ Wi,
                const float* __restrict__ Wh,
                float* __restrict__ out,
                int write_tail)
{
    extern __shared__ unsigned long long smu[];
    unsigned long long* Ws = smu + OFF_WS;
    unsigned long long* Hd = smu + OFF_HD;
    float*              Ps = reinterpret_cast<float*>(smu + OFF_PS);
    unsigned*           Aux = reinterpret_cast<unsigned*>(smu + OFF_AUX);

    const int tid = threadIdx.x;
    const int g   = blockIdx.x >> 4;
    const int c   = blockIdx.x & 15;
    const int bg0 = g * BG;
    const int jg0 = c * JC;

    // ---- prologue ----------------------------------------------------------
    if (tid == 0) Aux[0] = g_rnn_flag[blockIdx.x];   // all flags equal at launch

    {   // weights, column-permuted: dst(j) = (j>>2)*2 + ((j>>1)&1)*16 + (j&1)
        const int jl  = tid >> 3;                 // 0..31
        const int kpb = tid & 7;                  // 0..7
        const int dst = (jl >> 2) * 2 + ((jl >> 1) & 1) * 16 + (jl & 1);
        const float2* whp = reinterpret_cast<const float2*>(
            Wh + (size_t)(jg0 + jl) * kH);
        #pragma unroll
        for (int i = 0; i < KP_H / 8; ++i) {
            int kp = kpb + 8 * i;
            float2 v = __ldg(whp + kp);
            Ws[kp * WS_STRIDE + dst] = *reinterpret_cast<unsigned long long*>(&v);
        }
        const float2* wip = reinterpret_cast<const float2*>(
            Wi + (size_t)(jg0 + jl) * kI);
        #pragma unroll
        for (int i = 0; i < KP_X / 8; ++i) {
            int kp = kpb + 8 * i;
            float2 v = __ldg(wip + kp);
            Ws[(KP_H + kp) * WS_STRIDE + dst] =
                *reinterpret_cast<unsigned long long*>(&v);
        }
    }
    for (int e = tid; e < KP_H * HD_STRIDE; e += NTHR) Hd[e] = 0ull;

    // ---- per-thread geometry ------------------------------------------------
    const int w    = tid >> 5;           // warp 0..7
    const int lane = tid & 31;
    const int jq   = lane & 3;           // j octet
    const int bp   = (lane >> 2) & 3;    // batch quad
    const int kh   = lane >> 4;          // k-half (interleaved rows)

    // x staging role: row = KP_H + 16w + rl16, batches xbh..xbh+7
    const int rl16 = lane & 15;
    const int xbh  = (lane >> 4) * 8;

    // h readback role (R8 geometry)
    const int p    = lane & 15;
    const int bh   = (lane >> 4) * 8;
    const int pge8 = (p >> 3) & 1;

    unsigned* myflag = g_rnn_flag + blockIdx.x;

    // stage x[0]
    {
        const int row = KP_H + 16 * w + rl16;
        const int swz = 4 * ((row >> 3) & 3);
        #pragma unroll
        for (int i = 0; i < 8; ++i) {
            const int b = xbh + i;
            float2 v = __ldcg(reinterpret_cast<const float2*>(
                x + (size_t)(bg0 + b) * kI) + (16 * w + rl16));
            Hd[(size_t)row * HD_STRIDE + (b ^ swz)] =
                *reinterpret_cast<unsigned long long*>(&v);
        }
    }
    __syncthreads();
    const unsigned base = Aux[0];

    unsigned long long acc[32];

    // ---- x-part for t=0 ------------------------------------------------------
    {
        #pragma unroll
        for (int i = 0; i < 32; ++i) acc[i] = 0ull;
        #pragma unroll
        for (int s = 0; s < 2; ++s) {
            const int cs = (2 * w + s) & 3;
            const unsigned long long* wp =
                Ws + (size_t)(KP_H + 16 * w + 8 * s + kh) * WS_STRIDE + 4 * jq;
            const unsigned long long* hp =
                Hd + (size_t)(KP_H + 16 * w + 8 * s + kh) * HD_STRIDE + 4 * (bp ^ cs);
            #pragma unroll
            for (int i = 0; i < 4; ++i) {
                STEP32(wp, hp);
                wp += 2 * WS_STRIDE; hp += 2 * HD_STRIDE;
            }
        }
    }

    for (int t = 0; t < kT; ++t) {
        // ---- h-part: 16 kp (interleaved rows), 4 segments of 8 rows -----------
        #pragma unroll
        for (int s = 0; s < 4; ++s) {
            const int cs = s & 3;             // (4w+s)&3 == s&3
            const unsigned long long* wp =
                Ws + (size_t)(32 * w + 8 * s + kh) * WS_STRIDE + 4 * jq;
            const unsigned long long* hp =
                Hd + (size_t)(32 * w + 8 * s + kh) * HD_STRIDE + 4 * (bp ^ cs);
            #pragma unroll
            for (int i = 0; i < 4; ++i) {
                STEP32(wp, hp);
                wp += 2 * WS_STRIDE; hp += 2 * HD_STRIDE;
            }
        }

        // ---- scatter 32 partials (all-32-banks-distinct proven) ---------------
        {
            const int rowbase = (((2 * w + kh) * 16) + 4 * bp) * PS_STRIDE;
            #pragma unroll
            for (int bi = 0; bi < 4; ++bi) {
                #pragma unroll
                for (int mi = 0; mi < 8; ++mi) {
                    // mi -> local j: {0,1,4,5,2,3,6,7}
                    const int m = (mi < 2) ? mi : (mi < 4) ? mi + 2
                                 : (mi < 6) ? mi - 2 : mi;
                    float2 f = *reinterpret_cast<float2*>(&acc[mi * 4 + bi]);
                    Ps[rowbase + bi * PS_STRIDE + jq + 4 * m] = f.x + f.y;
                }
            }
        }

        // ---- prefetch x[t+1] ---------------------------------------------------
        float2 xv[8];
        if (t + 1 < kT) {
            const float* xb = x + (size_t)(t + 1) * kB * kI;
            #pragma unroll
            for (int i = 0; i < 8; ++i)
                xv[i] = __ldcg(reinterpret_cast<const float2*>(
                    xb + (size_t)(bg0 + xbh + i) * kI) + (16 * w + rl16));
        }
        __syncthreads();                                   // S1: Ps ready

        // ---- reduce 16 chunk-partials, tanh, store out[t] (float2) -------------
        {
            const int b  = tid >> 4;
            const int jp = tid & 15;
            const int j0 = 2 * jp, j1 = j0 + 1;
            const int cf0 = (j0 >> 3) + 4 * (j0 & 7);
            const int cf1 = (j1 >> 3) + 4 * (j1 & 7);
            float s0 = 0.f, s1 = 0.f;
            #pragma unroll
            for (int vc = 0; vc < 16; ++vc) {
                const int r = (vc * 16 + b) * PS_STRIDE;
                s0 += Ps[r + cf0];
                s1 += Ps[r + cf1];
            }
            float2 r2;
            r2.x = tanhf(s0);
            r2.y = tanhf(s1);
            size_t o = (size_t)t * kB * kH + (size_t)(bg0 + b) * kH + jg0 + j0;
            *reinterpret_cast<float2*>(out + o) = r2;
            if (t == kT - 1 && write_tail)
                *reinterpret_cast<float2*>(
                    out + (size_t)kT * kB * kH + (size_t)(bg0 + b) * kH + jg0 + j0) = r2;
        }
        if (t + 1 == kT) break;

        // ---- stage x[t+1] (warp-private rows) -----------------------------------
        {
            const int row = KP_H + 16 * w + rl16;
            const int swz = 4 * ((row >> 3) & 3);
            #pragma unroll
            for (int i = 0; i < 8; ++i) {
                const int b = xbh + i;
                Hd[(size_t)row * HD_STRIDE + (b ^ swz)] =
                    *reinterpret_cast<unsigned long long*>(&xv[i]);
            }
        }

        __threadfence();
        __syncthreads();                                   // S2

        if (tid == 0) {                                    // release out[t] once
            asm volatile("red.release.gpu.global.add.u32 [%0], %1;"
                         :: "l"(myflag), "r"(1u) : "memory");
        }

        // ---- x-part(t+1): overlaps release->visibility --------------------------
        {
            #pragma unroll
            for (int i = 0; i < 32; ++i) acc[i] = 0ull;
            #pragma unroll
            for (int s = 0; s < 2; ++s) {
                const int cs = (2 * w + s) & 3;
                const unsigned long long* wp =
                    Ws + (size_t)(KP_H + 16 * w + 8 * s + kh) * WS_STRIDE + 4 * jq;
                const unsigned long long* hp =
                    Hd + (size_t)(KP_H + 16 * w + 8 * s + kh) * HD_STRIDE + 4 * (bp ^ cs);
                #pragma unroll
                for (int i = 0; i < 4; ++i) {
                    STEP32(wp, hp);
                    wp += 2 * WS_STRIDE; hp += 2 * HD_STRIDE;
                }
            }
        }

        // ---- wait 2 producers, read h slices, stage (warp-private rows) ---------
        {
            const unsigned target = base + (unsigned)(t + 1);
            #pragma unroll
            for (int q = 0; q < 2; ++q) {
                const int pcta = 2 * w + q;
                const unsigned* fp = g_rnn_flag + (g * NC + pcta);
                unsigned cur;
                do {
                    asm volatile("ld.acquire.gpu.global.u32 %0, [%1];"
                                 : "=r"(cur) : "l"(fp) : "memory");
                } while ((int)(cur - target) < 0);

                const int hswz = 4 * ((2 * pcta + pge8) & 3);
                const float* hb = out + (size_t)t * kB * kH + (size_t)bg0 * kH
                                      + 32 * pcta + 2 * p;
                float2 hv[8];
                #pragma unroll
                for (int i = 0; i < 8; ++i) {
                    const int brd = ((((2 * i) & 6) | (i >> 2)) ^ pge8);
                    hv[i] = __ldcg(reinterpret_cast<const float2*>(
                        hb + (size_t)(bh + brd) * kH));
                }
                #pragma unroll
                for (int i = 0; i < 8; ++i) {
                    const int brd = ((((2 * i) & 6) | (i >> 2)) ^ pge8);
                    Hd[(16 * pcta + p) * HD_STRIDE + ((bh + brd) ^ hswz)] =
                        *reinterpret_cast<unsigned long long*>(&hv[i]);
                }
            }
            __syncwarp();
        }
    }
}

extern "C" void kernel_launch(void* const* d_in, const int* in_sizes, int n_in,
                              void* d_out, int out_size) {
    const float* x  = (const float*)d_in[0];   // [T,B,I]
    const float* Wi = (const float*)d_in[1];   // [H,I]
    const float* Wh = (const float*)d_in[2];   // [H,H]
    float* out = (float*)d_out;

    const long long main_elems = (long long)kT * kB * kH;
    int write_tail = ((long long)out_size >= main_elems + (long long)kB * kH) ? 1 : 0;

    cudaFuncSetAttribute(rnn_wide_kernel,
                         cudaFuncAttributeMaxDynamicSharedMemorySize,
                         (int)SMEM_BYTES);
    rnn_wide_kernel<<<NG * NC, NTHR, SMEM_BYTES>>>(x, Wi, Wh, out, write_tail);
}

// round 14
// speedup vs baseline: 1.0001x; 1.0001x over previous
#include <cuda_runtime.h>
#include <stdint.h>

// ---------------------------------------------------------------------------
// Persistent fp32 RNN, k-pair packed f32x2, WIDE thread tile (j8 x b4).
//
// out[t] = tanh(x[t] @ Wi^T + h @ Wh^T),  h = out[t]
//
// 8 batch-groups x 16 H-slice CTAs = 128 CTAs, 256 threads (8 warps),
// 255-reg budget. Lanes: jq=lane&3 (8 j's), bp=(lane>>2)&3 (4 b's),
// kh=lane>>4 (k-half; interleaved kp rows). 16 virtual k-chunks x 24 kp.
// Inner: 6 LDS.128 -> 32 fma2 per kp (0.67 FMA/B vs 0.5 before).
// Sync protocol identical to R6 (best known): threadfence + S2 + tid0
// release; per-warp producer spin (2 producers/warp, R8 geometry).
// ---------------------------------------------------------------------------

namespace {
constexpr int kT = 1024, kB = 128, kI = 256, kH = 512;
constexpr int NG = 8, BG = 16, NC = 16, JC = 32;
constexpr int NTHR = 256, NWARP = 8;
constexpr int KP_H = kH / 2;          // 256
constexpr int KP_X = kI / 2;          // 128
constexpr int KPT  = KP_H + KP_X;     // 384

constexpr int WS_STRIDE = 34;         // u64 per weight row
constexpr int HD_STRIDE = 18;         // u64 per Hd row (16 cols + pad)
constexpr int PS_STRIDE = 33;         // floats per Ps row (odd -> bank spread)
constexpr int PS_ROWS   = 32 * 8;     // 16 chunks x 16 batches? -> 256 rows
constexpr int PS_FLOATS = PS_ROWS * PS_STRIDE;      // 8448

constexpr int OFF_WS = 0;
constexpr int OFF_HD = KPT * WS_STRIDE;             // 13056 u64
constexpr int OFF_PS = OFF_HD + KPT * HD_STRIDE;    // 19968 u64
constexpr int OFF_AUX = OFF_PS + (PS_FLOATS + 1) / 2;
constexpr int SMEM_U64 = OFF_AUX + 1;
constexpr size_t SMEM_BYTES = size_t(SMEM_U64) * 8; // ~189 KB
}

__device__ unsigned g_rnn_flag[NG * NC];   // zero-init; monotonic forever

__device__ __forceinline__ void fma2(unsigned long long& acc,
                                     unsigned long long a,
                                     unsigned long long b) {
    asm("fma.rn.f32x2 %0, %1, %2, %0;" : "+l"(acc) : "l"(a), "l"(b));
}

// one kp row: 8 j (w0..w3, mi order {0,1,4,5,2,3,6,7}) x 4 b (h0,h1)
#define STEP32(wp, hp)                                                       \
    do {                                                                     \
        const ulonglong2 w0 = *reinterpret_cast<const ulonglong2*>(wp);      \
        const ulonglong2 w1 = *reinterpret_cast<const ulonglong2*>((wp)+2);  \
        const ulonglong2 w2 = *reinterpret_cast<const ulonglong2*>((wp)+16); \
        const ulonglong2 w3 = *reinterpret_cast<const ulonglong2*>((wp)+18); \
        const ulonglong2 h0 = *reinterpret_cast<const ulonglong2*>(hp);      \
        const ulonglong2 h1 = *reinterpret_cast<const ulonglong2*>((hp)+2);  \
        fma2(acc[0],  w0.x, h0.x); fma2(acc[1],  w0.x, h0.y);                \
        fma2(acc[2],  w0.x, h1.x); fma2(acc[3],  w0.x, h1.y);                \
        fma2(acc[4],  w0.y, h0.x); fma2(acc[5],  w0.y, h0.y);                \
        fma2(acc[6],  w0.y, h1.x); fma2(acc[7],  w0.y, h1.y);                \
        fma2(acc[8],  w1.x, h0.x); fma2(acc[9],  w1.x, h0.y);                \
        fma2(acc[10], w1.x, h1.x); fma2(acc[11], w1.x, h1.y);                \
        fma2(acc[12], w1.y, h0.x); fma2(acc[13], w1.y, h0.y);                \
        fma2(acc[14], w1.y, h1.x); fma2(acc[15], w1.y, h1.y);                \
        fma2(acc[16], w2.x, h0.x); fma2(acc[17], w2.x, h0.y);                \
        fma2(acc[18], w2.x, h1.x); fma2(acc[19], w2.x, h1.y);                \
        fma2(acc[20], w2.y, h0.x); fma2(acc[21], w2.y, h0.y);                \
        fma2(acc[22], w2.y, h1.x); fma2(acc[23], w2.y, h1.y);                \
        fma2(acc[24], w3.x, h0.x); fma2(acc[25], w3.x, h0.y);                \
        fma2(acc[26], w3.x, h1.x); fma2(acc[27], w3.x, h1.y);                \
        fma2(acc[28], w3.y, h0.x); fma2(acc[29], w3.y, h0.y);                \
        fma2(acc[30], w3.y, h1.x); fma2(acc[31], w3.y, h1.y);                \
    } while (0)

__global__ void __launch_bounds__(NTHR, 1)
rnn_wide_kernel(const float* __restrict__ x,
                const float* __restrict__ Wi,
                const float* __restrict__ Wh,
                float* __restrict__ out,
                int write_tail)
{
    extern __shared__ unsigned long long smu[];
    unsigned long long* Ws = smu + OFF_WS;
    unsigned long long* Hd = smu + OFF_HD;
    float*              Ps = reinterpret_cast<float*>(smu + OFF_PS);
    unsigned*           Aux = reinterpret_cast<unsigned*>(smu + OFF_AUX);

    const int tid = threadIdx.x;
    const int g   = blockIdx.x >> 4;
    const int c   = blockIdx.x & 15;
    const int bg0 = g * BG;
    const int jg0 = c * JC;

    // ---- prologue ----------------------------------------------------------
    if (tid == 0) Aux[0] = g_rnn_flag[blockIdx.x];   // all flags equal at launch

    {   // weights, column-permuted: dst(j) = (j>>2)*2 + ((j>>1)&1)*16 + (j&1)
        const int jl  = tid >> 3;                 // 0..31
        const int kpb = tid & 7;                  // 0..7
        const int dst = (jl >> 2) * 2 + ((jl >> 1) & 1) * 16 + (jl & 1);
        const float2* whp = reinterpret_cast<const float2*>(
            Wh + (size_t)(jg0 + jl) * kH);
        #pragma unroll
        for (int i = 0; i < KP_H / 8; ++i) {
            int kp = kpb + 8 * i;
            float2 v = __ldg(whp + kp);
            Ws[kp * WS_STRIDE + dst] = *reinterpret_cast<unsigned long long*>(&v);
        }
        const float2* wip = reinterpret_cast<const float2*>(
            Wi + (size_t)(jg0 + jl) * kI);
        #pragma unroll
        for (int i = 0; i < KP_X / 8; ++i) {
            int kp = kpb + 8 * i;
            float2 v = __ldg(wip + kp);
            Ws[(KP_H + kp) * WS_STRIDE + dst] =
                *reinterpret_cast<unsigned long long*>(&v);
        }
    }
    for (int e = tid; e < KP_H * HD_STRIDE; e += NTHR) Hd[e] = 0ull;

    // ---- per-thread geometry ------------------------------------------------
    const int w    = tid >> 5;           // warp 0..7
    const int lane = tid & 31;
    const int jq   = lane & 3;           // j octet
    const int bp   = (lane >> 2) & 3;    // batch quad
    const int kh   = lane >> 4;          // k-half (interleaved rows)

    // x staging role: row = KP_H + 16w + rl16, batches xbh..xbh+7
    const int rl16 = lane & 15;
    const int xbh  = (lane >> 4) * 8;

    // h readback role (R8 geometry)
    const int p    = lane & 15;
    const int bh   = (lane >> 4) * 8;
    const int pge8 = (p >> 3) & 1;

    unsigned* myflag = g_rnn_flag + blockIdx.x;

    // stage x[0]
    {
        const int row = KP_H + 16 * w + rl16;
        const int swz = 4 * ((row >> 3) & 3);
        #pragma unroll
        for (int i = 0; i < 8; ++i) {
            const int b = xbh + i;
            float2 v = __ldcg(reinterpret_cast<const float2*>(
                x + (size_t)(bg0 + b) * kI) + (16 * w + rl16));
            Hd[(size_t)row * HD_STRIDE + (b ^ swz)] =
                *reinterpret_cast<unsigned long long*>(&v);
        }
    }
    __syncthreads();
    const unsigned base = Aux[0];

    unsigned long long acc[32];

    // ---- x-part for t=0 ------------------------------------------------------
    {
        #pragma unroll
        for (int i = 0; i < 32; ++i) acc[i] = 0ull;
        #pragma unroll
        for (int s = 0; s < 2; ++s) {
            const int cs = (2 * w + s) & 3;
            const unsigned long long* wp =
                Ws + (size_t)(KP_H + 16 * w + 8 * s + kh) * WS_STRIDE + 4 * jq;
            const unsigned long long* hp =
                Hd + (size_t)(KP_H + 16 * w + 8 * s + kh) * HD_STRIDE + 4 * (bp ^ cs);
            #pragma unroll
            for (int i = 0; i < 4; ++i) {
                STEP32(wp, hp);
                wp += 2 * WS_STRIDE; hp += 2 * HD_STRIDE;
            }
        }
    }

    for (int t = 0; t < kT; ++t) {
        // ---- h-part: 16 kp (interleaved rows), 4 segments of 8 rows -----------
        #pragma unroll
        for (int s = 0; s < 4; ++s) {
            const int cs = s & 3;             // (4w+s)&3 == s&3
            const unsigned long long* wp =
                Ws + (size_t)(32 * w + 8 * s + kh) * WS_STRIDE + 4 * jq;
            const unsigned long long* hp =
                Hd + (size_t)(32 * w + 8 * s + kh) * HD_STRIDE + 4 * (bp ^ cs);
            #pragma unroll
            for (int i = 0; i < 4; ++i) {
                STEP32(wp, hp);
                wp += 2 * WS_STRIDE; hp += 2 * HD_STRIDE;
            }
        }

        // ---- scatter 32 partials (all-32-banks-distinct proven) ---------------
        {
            const int rowbase = (((2 * w + kh) * 16) + 4 * bp) * PS_STRIDE;
            #pragma unroll
            for (int bi = 0; bi < 4; ++bi) {
                #pragma unroll
                for (int mi = 0; mi < 8; ++mi) {
                    // mi -> local j: {0,1,4,5,2,3,6,7}
                    const int m = (mi < 2) ? mi : (mi < 4) ? mi + 2
                                 : (mi < 6) ? mi - 2 : mi;
                    float2 f = *reinterpret_cast<float2*>(&acc[mi * 4 + bi]);
                    Ps[rowbase + bi * PS_STRIDE + jq + 4 * m] = f.x + f.y;
                }
            }
        }

        // ---- prefetch x[t+1] ---------------------------------------------------
        float2 xv[8];
        if (t + 1 < kT) {
            const float* xb = x + (size_t)(t + 1) * kB * kI;
            #pragma unroll
            for (int i = 0; i < 8; ++i)
                xv[i] = __ldcg(reinterpret_cast<const float2*>(
                    xb + (size_t)(bg0 + xbh + i) * kI) + (16 * w + rl16));
        }
        __syncthreads();                                   // S1: Ps ready

        // ---- reduce 16 chunk-partials, tanh, store out[t] (float2) -------------
        {
            const int b  = tid >> 4;
            const int jp = tid & 15;
            const int j0 = 2 * jp, j1 = j0 + 1;
            const int cf0 = (j0 >> 3) + 4 * (j0 & 7);
            const int cf1 = (j1 >> 3) + 4 * (j1 & 7);
            float s0 = 0.f, s1 = 0.f;
            #pragma unroll
            for (int vc = 0; vc < 16; ++vc) {
                const int r = (vc * 16 + b) * PS_STRIDE;
                s0 += Ps[r + cf0];
                s1 += Ps[r + cf1];
            }
            float2 r2;
            r2.x = tanhf(s0);
            r2.y = tanhf(s1);
            size_t o = (size_t)t * kB * kH + (size_t)(bg0 + b) * kH + jg0 + j0;
            *reinterpret_cast<float2*>(out + o) = r2;
            if (t == kT - 1 && write_tail)
                *reinterpret_cast<float2*>(
                    out + (size_t)kT * kB * kH + (size_t)(bg0 + b) * kH + jg0 + j0) = r2;
        }
        if (t + 1 == kT) break;

        // ---- stage x[t+1] (warp-private rows) -----------------------------------
        {
            const int row = KP_H + 16 * w + rl16;
            const int swz = 4 * ((row >> 3) & 3);
            #pragma unroll
            for (int i = 0; i < 8; ++i) {
                const int b = xbh + i;
                Hd[(size_t)row * HD_STRIDE + (b ^ swz)] =
                    *reinterpret_cast<unsigned long long*>(&xv[i]);
            }
        }

        __threadfence();
        __syncthreads();                                   // S2

        if (tid == 0) {                                    // release out[t] once
            asm volatile("red.release.gpu.global.add.u32 [%0], %1;"
                         :: "l"(myflag), "r"(1u) : "memory");
        }

        // ---- x-part(t+1): overlaps release->visibility --------------------------
        {
            #pragma unroll
            for (int i = 0; i < 32; ++i) acc[i] = 0ull;
            #pragma unroll
            for (int s = 0; s < 2; ++s) {
                const int cs = (2 * w + s) & 3;
                const unsigned long long* wp =
                    Ws + (size_t)(KP_H + 16 * w + 8 * s + kh) * WS_STRIDE + 4 * jq;
                const unsigned long long* hp =
                    Hd + (size_t)(KP_H + 16 * w + 8 * s + kh) * HD_STRIDE + 4 * (bp ^ cs);
                #pragma unroll
                for (int i = 0; i < 4; ++i) {
                    STEP32(wp, hp);
                    wp += 2 * WS_STRIDE; hp += 2 * HD_STRIDE;
                }
            }
        }

        // ---- wait 2 producers, read h slices, stage (warp-private rows) ---------
        {
            const unsigned target = base + (unsigned)(t + 1);
            #pragma unroll
            for (int q = 0; q < 2; ++q) {
                const int pcta = 2 * w + q;
                const unsigned* fp = g_rnn_flag + (g * NC + pcta);
                unsigned cur;
                do {
                    asm volatile("ld.acquire.gpu.global.u32 %0, [%1];"
                                 : "=r"(cur) : "l"(fp) : "memory");
                } while ((int)(cur - target) < 0);

                const int hswz = 4 * ((2 * pcta + pge8) & 3);
                const float* hb = out + (size_t)t * kB * kH + (size_t)bg0 * kH
                                      + 32 * pcta + 2 * p;
                float2 hv[8];
                #pragma unroll
                for (int i = 0; i < 8; ++i) {
                    const int brd = ((((2 * i) & 6) | (i >> 2)) ^ pge8);
                    hv[i] = __ldcg(reinterpret_cast<const float2*>(
                        hb + (size_t)(bh + brd) * kH));
                }
                #pragma unroll
                for (int i = 0; i < 8; ++i) {
                    const int brd = ((((2 * i) & 6) | (i >> 2)) ^ pge8);
                    Hd[(16 * pcta + p) * HD_STRIDE + ((bh + brd) ^ hswz)] =
                        *reinterpret_cast<unsigned long long*>(&hv[i]);
                }
            }
            __syncwarp();
        }
    }
}

extern "C" void kernel_launch(void* const* d_in, const int* in_sizes, int n_in,
                              void* d_out, int out_size) {
    const float* x  = (const float*)d_in[0];   // [T,B,I]
    const float* Wi = (const float*)d_in[1];   // [H,I]
    const float* Wh = (const float*)d_in[2];   // [H,H]
    float* out = (float*)d_out;

    const long long main_elems = (long long)kT * kB * kH;
    int write_tail = ((long long)out_size >= main_elems + (long long)kB * kH) ? 1 : 0;

    cudaFuncSetAttribute(rnn_wide_kernel,
                         cudaFuncAttributeMaxDynamicSharedMemorySize,
                         (int)SMEM_BYTES);
    rnn_wide_kernel<<<NG * NC, NTHR, SMEM_BYTES>>>(x, Wi, Wh, out, write_tail);
}